// round 7
// baseline (speedup 1.0000x reference)
#include <cuda_runtime.h>

// Regional Interaction Module — v7: persistent CTAs + dynamic work queue.
// 608 CTAs (4/SM on 152 SMs) pull 1024-float4 chunks from a global atomic
// counter -> no wave-quantization tail, no CTA-spread straggling; DRAM demand
// stays flat to the end. Pixel math = v6 (tanh.approx sigmoid, composite
// folded weights, depth-1 load pipelining within each chunk).

#define PLANE4   65536               // 512*512/4 float4 per plane
#define ITERS    4
#define THREADS  256
#define CHUNK    (THREADS * ITERS)   // 1024 float4 groups per chunk
#define GRID     608                 // 152 SMs * 4 CTAs/SM

__device__ unsigned int g_next_chunk;

__global__ void rim_reset_kernel() { g_next_chunk = GRID; }

__device__ __forceinline__ float tanh_fast(float x) {
    float y;
    asm("tanh.approx.f32 %0, %1;" : "=f"(y) : "f"(x));
    return y;
}

template <bool TAIL>
__global__ void __launch_bounds__(THREADS, 4)
rim_kernel(const float* __restrict__ img, const float* __restrict__ mask,
           const float* __restrict__ qi_w, const float* __restrict__ qi_b,
           const float* __restrict__ ki_w, const float* __restrict__ ki_b,
           const float* __restrict__ vi_w, const float* __restrict__ vi_b,
           const float* __restrict__ qr_w, const float* __restrict__ qr_b,
           const float* __restrict__ kr_w, const float* __restrict__ kr_b,
           const float* __restrict__ vr_w, const float* __restrict__ vr_b,
           const float* __restrict__ fu_w, const float* __restrict__ fu_b,
           float* __restrict__ out, int n_q, int n_chunks)
{
    // ---- per-thread coefficient setup (L1-broadcast loads) ----
    const float qiw0 = 0.5f * qi_w[0], qiw1 = 0.5f * qi_w[1],
                qiw2 = 0.5f * qi_w[2], qib  = 0.5f * qi_b[0];
    const float kiw0 = ki_w[0], kiw1 = ki_w[1], kiw2 = ki_w[2], kib = ki_b[0];
    const float qrw = 0.5f * qr_w[0], qrb = 0.5f * qr_b[0];
    const float krw = kr_w[0], krb = kr_b[0];
    const float vrw = 0.5f * vr_w[0], vrb = 0.5f * vr_b[0];

    float viw[9], vib[3];
    #pragma unroll
    for (int i = 0; i < 9; i++) viw[i] = vi_w[i];
    #pragma unroll
    for (int i = 0; i < 3; i++) vib[i] = vi_b[i];

    float WA[3][3], WB[3][3], bA[3], bB[3], Sa[3], Sb[3], fub[3];
    #pragma unroll
    for (int c = 0; c < 3; c++) {
        const float a0 = fu_w[c * 6 + 0], a1 = fu_w[c * 6 + 1], a2 = fu_w[c * 6 + 2];
        const float b0 = fu_w[c * 6 + 3], b1 = fu_w[c * 6 + 4], b2 = fu_w[c * 6 + 5];
        Sa[c] = a0 + a1 + a2;
        Sb[c] = b0 + b1 + b2;
        #pragma unroll
        for (int i = 0; i < 3; i++) {
            WA[c][i] = a0 * viw[0 * 3 + i] + a1 * viw[1 * 3 + i] + a2 * viw[2 * 3 + i];
            WB[c][i] = b0 * viw[0 * 3 + i] + b1 * viw[1 * 3 + i] + b2 * viw[2 * 3 + i];
        }
        bA[c]  = a0 * vib[0] + a1 * vib[1] + a2 * vib[2];
        bB[c]  = b0 * vib[0] + b1 * vib[1] + b2 * vib[2];
        fub[c] = fu_b[c];
    }

    auto pixel = [&](float r, float g, float bl, float m,
                     float& o0, float& o1, float& o2) {
        const float qih = fmaf(qiw2, bl, fmaf(qiw1, g, fmaf(qiw0, r, qib)));
        const float ki  = fmaf(kiw2, bl, fmaf(kiw1, g, fmaf(kiw0, r, kib)));
        const float qrh = fmaf(qrw, m, qrb);
        const float kr  = fmaf(krw, m, krb);
        const float vrh = fmaf(vrw, m, vrb);
        const float t1 = tanh_fast(qih * ki);
        const float t2 = tanh_fast(qih * kr);
        const float t3 = tanh_fast(qrh * kr);
        const float t4 = tanh_fast(qrh * ki);
        const float s1 = fmaf(t1, 0.5f, 0.5f);
        const float s4 = fmaf(t4, 0.5f, 0.5f);
        const float p2 = fmaf(vrh, t2, vrh);
        const float p3 = fmaf(vrh, t3, vrh);
        float o[3];
        #pragma unroll
        for (int c = 0; c < 3; c++) {
            const float A  = fmaf(WA[c][2], bl, fmaf(WA[c][1], g, fmaf(WA[c][0], r, bA[c])));
            const float Bv = fmaf(WB[c][2], bl, fmaf(WB[c][1], g, fmaf(WB[c][0], r, bB[c])));
            float f = fmaf(s1, A, fub[c]);
            f = fmaf(s4, Bv, f);
            f = fmaf(p2, Sa[c], f);
            f = fmaf(p3, Sb[c], f);
            o[c] = f;
        }
        o0 = o[0]; o1 = o[1]; o2 = o[2];
    };

    const float4* img4  = reinterpret_cast<const float4*>(img);
    const float4* mask4 = reinterpret_cast<const float4*>(mask);
    float4*       out4  = reinterpret_cast<float4*>(out);

    __shared__ int s_chunk;
    int chunk = blockIdx.x;

    while (chunk < n_chunks) {
        const int q0 = chunk * CHUNK + threadIdx.x;

        // ---- depth-1 pipelined processing of this chunk ----
        int q    = q0;
        bool v0  = !TAIL || (q < n_q);
        int base = (q >> 16) * (3 * PLANE4) + (q & (PLANE4 - 1));

        float4 R, G, Bc, M;
        if (v0) {
            R  = img4[base];
            G  = img4[base + PLANE4];
            Bc = img4[base + 2 * PLANE4];
            M  = mask4[q];
        }

        #pragma unroll
        for (int k = 0; k < ITERS; k++) {
            const bool valid = !TAIL || (q0 + k * THREADS < n_q);
            float4 Rn, Gn, Bn, Mn;
            int basen = base;
            if (k + 1 < ITERS) {
                const int qn = q0 + (k + 1) * THREADS;
                const bool vn = !TAIL || (qn < n_q);
                basen = (qn >> 16) * (3 * PLANE4) + (qn & (PLANE4 - 1));
                if (vn) {
                    Rn = img4[basen];
                    Gn = img4[basen + PLANE4];
                    Bn = img4[basen + 2 * PLANE4];
                    Mn = mask4[qn];
                }
            }

            if (valid) {
                float4 O0, O1, O2;
                pixel(R.x, G.x, Bc.x, M.x, O0.x, O1.x, O2.x);
                pixel(R.y, G.y, Bc.y, M.y, O0.y, O1.y, O2.y);
                pixel(R.z, G.z, Bc.z, M.z, O0.z, O1.z, O2.z);
                pixel(R.w, G.w, Bc.w, M.w, O0.w, O1.w, O2.w);
                out4[base]              = O0;
                out4[base + PLANE4]     = O1;
                out4[base + 2 * PLANE4] = O2;
            }

            R = Rn; G = Gn; Bc = Bn; M = Mn;
            base = basen;
        }

        // ---- grab next chunk from the global queue ----
        if (threadIdx.x == 0) s_chunk = (int)atomicAdd(&g_next_chunk, 1u);
        __syncthreads();
        chunk = s_chunk;
        __syncthreads();   // protect s_chunk against next iteration's write
    }
}

extern "C" void kernel_launch(void* const* d_in, const int* in_sizes, int n_in,
                              void* d_out, int out_size)
{
    const float* img  = (const float*)d_in[0];
    const float* mask = (const float*)d_in[1];
    const float* qi_w = (const float*)d_in[2];
    const float* qi_b = (const float*)d_in[3];
    const float* ki_w = (const float*)d_in[4];
    const float* ki_b = (const float*)d_in[5];
    const float* vi_w = (const float*)d_in[6];
    const float* vi_b = (const float*)d_in[7];
    const float* qr_w = (const float*)d_in[8];
    const float* qr_b = (const float*)d_in[9];
    const float* kr_w = (const float*)d_in[10];
    const float* kr_b = (const float*)d_in[11];
    const float* vr_w = (const float*)d_in[12];
    const float* vr_b = (const float*)d_in[13];
    const float* fu_w = (const float*)d_in[14];
    const float* fu_b = (const float*)d_in[15];

    const int n_pix    = in_sizes[1];        // B*H*W
    const int n_q      = n_pix / 4;          // float4 groups
    const int n_chunks = (n_q + CHUNK - 1) / CHUNK;
    const int grid     = (n_chunks < GRID) ? n_chunks : GRID;

    rim_reset_kernel<<<1, 1>>>();

    if (n_q % CHUNK == 0) {
        rim_kernel<false><<<grid, THREADS>>>(
            img, mask, qi_w, qi_b, ki_w, ki_b, vi_w, vi_b,
            qr_w, qr_b, kr_w, kr_b, vr_w, vr_b, fu_w, fu_b,
            (float*)d_out, n_q, n_chunks);
    } else {
        rim_kernel<true><<<grid, THREADS>>>(
            img, mask, qi_w, qi_b, ki_w, ki_b, vi_w, vi_b,
            qr_w, qr_b, kr_w, kr_b, vr_w, vr_b, fu_w, fu_b,
            (float*)d_out, n_q, n_chunks);
    }
}

// round 8
// speedup vs baseline: 1.0394x; 1.0394x over previous
#include <cuda_runtime.h>

// Regional Interaction Module — v8 (= v6, the roofline kernel).
// Seven rounds established this problem is bound by the LTS chip-traffic cap
// (~6300 B/cyc ≈ 6.8 TB/s): 233.5 MB of irreducible L2 traffic / 34.4 us.
// Occupancy, MLP, instruction count, load balance all proven non-binding.
// Kernel: fully fused per-pixel closed form, composite folded weights,
// tanh.approx sigmoid (sigmoid(x) = 0.5 + 0.5*tanh(x/2), halves folded into
// weights), depth-1 load pipelining, single launch.

#define HW       (512 * 512)
#define PLANE4   (HW / 4)          // 65536 float4 per plane
#define ITERS    4
#define THREADS  256

__device__ __forceinline__ float tanh_fast(float x) {
    float y;
    asm("tanh.approx.f32 %0, %1;" : "=f"(y) : "f"(x));
    return y;
}

template <bool TAIL>
__global__ void __launch_bounds__(THREADS, 4)
rim_kernel(const float* __restrict__ img, const float* __restrict__ mask,
           const float* __restrict__ qi_w, const float* __restrict__ qi_b,
           const float* __restrict__ ki_w, const float* __restrict__ ki_b,
           const float* __restrict__ vi_w, const float* __restrict__ vi_b,
           const float* __restrict__ qr_w, const float* __restrict__ qr_b,
           const float* __restrict__ kr_w, const float* __restrict__ kr_b,
           const float* __restrict__ vr_w, const float* __restrict__ vr_b,
           const float* __restrict__ fu_w, const float* __restrict__ fu_b,
           float* __restrict__ out, int n_q)
{
    // ---- per-thread coefficient setup (L1-broadcast loads) ----
    // qi, qr, vr pre-scaled by 0.5 for the tanh-based sigmoid.
    const float qiw0 = 0.5f * qi_w[0], qiw1 = 0.5f * qi_w[1],
                qiw2 = 0.5f * qi_w[2], qib  = 0.5f * qi_b[0];
    const float kiw0 = ki_w[0], kiw1 = ki_w[1], kiw2 = ki_w[2], kib = ki_b[0];
    const float qrw = 0.5f * qr_w[0], qrb = 0.5f * qr_b[0];
    const float krw = kr_w[0], krb = kr_b[0];
    const float vrw = 0.5f * vr_w[0], vrb = 0.5f * vr_b[0];

    float viw[9], vib[3];
    #pragma unroll
    for (int i = 0; i < 9; i++) viw[i] = vi_w[i];
    #pragma unroll
    for (int i = 0; i < 3; i++) vib[i] = vi_b[i];

    float WA[3][3], WB[3][3], bA[3], bB[3], Sa[3], Sb[3], fub[3];
    #pragma unroll
    for (int c = 0; c < 3; c++) {
        const float a0 = fu_w[c * 6 + 0], a1 = fu_w[c * 6 + 1], a2 = fu_w[c * 6 + 2];
        const float b0 = fu_w[c * 6 + 3], b1 = fu_w[c * 6 + 4], b2 = fu_w[c * 6 + 5];
        Sa[c] = a0 + a1 + a2;
        Sb[c] = b0 + b1 + b2;
        #pragma unroll
        for (int i = 0; i < 3; i++) {
            WA[c][i] = a0 * viw[0 * 3 + i] + a1 * viw[1 * 3 + i] + a2 * viw[2 * 3 + i];
            WB[c][i] = b0 * viw[0 * 3 + i] + b1 * viw[1 * 3 + i] + b2 * viw[2 * 3 + i];
        }
        bA[c]  = a0 * vib[0] + a1 * vib[1] + a2 * vib[2];
        bB[c]  = b0 * vib[0] + b1 * vib[1] + b2 * vib[2];
        fub[c] = fu_b[c];
    }

    auto pixel = [&](float r, float g, float bl, float m,
                     float& o0, float& o1, float& o2) {
        const float qih = fmaf(qiw2, bl, fmaf(qiw1, g, fmaf(qiw0, r, qib)));
        const float ki  = fmaf(kiw2, bl, fmaf(kiw1, g, fmaf(kiw0, r, kib)));
        const float qrh = fmaf(qrw, m, qrb);
        const float kr  = fmaf(krw, m, krb);
        const float vrh = fmaf(vrw, m, vrb);
        // sigmoid(a*b) = 0.5 + 0.5*tanh(0.5*a*b)
        const float t1 = tanh_fast(qih * ki);
        const float t2 = tanh_fast(qih * kr);
        const float t3 = tanh_fast(qrh * kr);
        const float t4 = tanh_fast(qrh * ki);
        const float s1 = fmaf(t1, 0.5f, 0.5f);
        const float s4 = fmaf(t4, 0.5f, 0.5f);
        const float p2 = fmaf(vrh, t2, vrh);   // v_r * sigmoid(q_i*k_r)
        const float p3 = fmaf(vrh, t3, vrh);   // v_r * sigmoid(q_r*k_r)
        float o[3];
        #pragma unroll
        for (int c = 0; c < 3; c++) {
            const float A  = fmaf(WA[c][2], bl, fmaf(WA[c][1], g, fmaf(WA[c][0], r, bA[c])));
            const float Bv = fmaf(WB[c][2], bl, fmaf(WB[c][1], g, fmaf(WB[c][0], r, bB[c])));
            float f = fmaf(s1, A, fub[c]);
            f = fmaf(s4, Bv, f);
            f = fmaf(p2, Sa[c], f);
            f = fmaf(p3, Sb[c], f);
            o[c] = f;
        }
        o0 = o[0]; o1 = o[1]; o2 = o[2];
    };

    const float4* img4  = reinterpret_cast<const float4*>(img);
    const float4* mask4 = reinterpret_cast<const float4*>(mask);
    float4*       out4  = reinterpret_cast<float4*>(out);

    const int tid    = blockIdx.x * THREADS + threadIdx.x;
    const int stride = gridDim.x * THREADS;

    if (!TAIL) {
        // ---- pipelined main path: prefetch iter k+1 before computing iter k ----
        int q    = tid;
        int base = (q >> 16) * (3 * PLANE4) + (q & (PLANE4 - 1));

        float4 R  = img4[base];
        float4 G  = img4[base + PLANE4];
        float4 Bc = img4[base + 2 * PLANE4];
        float4 M  = mask4[q];

        #pragma unroll
        for (int k = 0; k < ITERS; k++) {
            float4 Rn, Gn, Bn, Mn;
            int basen = base;
            if (k + 1 < ITERS) {
                const int qn = tid + (k + 1) * stride;
                basen = (qn >> 16) * (3 * PLANE4) + (qn & (PLANE4 - 1));
                Rn = img4[basen];
                Gn = img4[basen + PLANE4];
                Bn = img4[basen + 2 * PLANE4];
                Mn = mask4[qn];
            }

            float4 O0, O1, O2;
            pixel(R.x, G.x, Bc.x, M.x, O0.x, O1.x, O2.x);
            pixel(R.y, G.y, Bc.y, M.y, O0.y, O1.y, O2.y);
            pixel(R.z, G.z, Bc.z, M.z, O0.z, O1.z, O2.z);
            pixel(R.w, G.w, Bc.w, M.w, O0.w, O1.w, O2.w);

            out4[base]              = O0;
            out4[base + PLANE4]     = O1;
            out4[base + 2 * PLANE4] = O2;

            R = Rn; G = Gn; Bc = Bn; M = Mn;
            base = basen;
        }
    } else {
        for (int k = 0; k < ITERS; k++) {
            const int q = tid + k * stride;
            if (q >= n_q) break;
            const int base = (q >> 16) * (3 * PLANE4) + (q & (PLANE4 - 1));
            const float4 R  = img4[base];
            const float4 G  = img4[base + PLANE4];
            const float4 Bc = img4[base + 2 * PLANE4];
            const float4 M  = mask4[q];
            float4 O0, O1, O2;
            pixel(R.x, G.x, Bc.x, M.x, O0.x, O1.x, O2.x);
            pixel(R.y, G.y, Bc.y, M.y, O0.y, O1.y, O2.y);
            pixel(R.z, G.z, Bc.z, M.z, O0.z, O1.z, O2.z);
            pixel(R.w, G.w, Bc.w, M.w, O0.w, O1.w, O2.w);
            out4[base]              = O0;
            out4[base + PLANE4]     = O1;
            out4[base + 2 * PLANE4] = O2;
        }
    }
}

extern "C" void kernel_launch(void* const* d_in, const int* in_sizes, int n_in,
                              void* d_out, int out_size)
{
    const float* img  = (const float*)d_in[0];
    const float* mask = (const float*)d_in[1];
    const float* qi_w = (const float*)d_in[2];
    const float* qi_b = (const float*)d_in[3];
    const float* ki_w = (const float*)d_in[4];
    const float* ki_b = (const float*)d_in[5];
    const float* vi_w = (const float*)d_in[6];
    const float* vi_b = (const float*)d_in[7];
    const float* qr_w = (const float*)d_in[8];
    const float* qr_b = (const float*)d_in[9];
    const float* kr_w = (const float*)d_in[10];
    const float* kr_b = (const float*)d_in[11];
    const float* vr_w = (const float*)d_in[12];
    const float* vr_b = (const float*)d_in[13];
    const float* fu_w = (const float*)d_in[14];
    const float* fu_b = (const float*)d_in[15];

    const int n_pix = in_sizes[1];       // B*H*W
    const int n_q   = n_pix / 4;
    const int per_block = THREADS * ITERS;

    if (n_q % per_block == 0) {
        rim_kernel<false><<<n_q / per_block, THREADS>>>(
            img, mask, qi_w, qi_b, ki_w, ki_b, vi_w, vi_b,
            qr_w, qr_b, kr_w, kr_b, vr_w, vr_b, fu_w, fu_b,
            (float*)d_out, n_q);
    } else {
        rim_kernel<true><<<(n_q + per_block - 1) / per_block, THREADS>>>(
            img, mask, qi_w, qi_b, ki_w, ki_b, vi_w, vi_b,
            qr_w, qr_b, kr_w, kr_b, vr_w, vr_b, fu_w, fu_b,
            (float*)d_out, n_q);
    }
}

// round 9
// speedup vs baseline: 1.0402x; 1.0008x over previous
#include <cuda_runtime.h>

// Regional Interaction Module — FINAL (v8 held at the roofline).
//
// Roofline analysis (8 rounds): the problem moves 233.5 MB through L2
// (img 100 MB + mask 33.5 MB reads, out 100 MB writes, all single-touch,
// fully coalesced fp32 — byte count irreducible). Measured kernel time
// 34.4 us -> 6.78 TB/s L2<->SM, which equals the B300 LTS chip-throughput
// cap (~6300 B/cyc, path-independent). Occupancy (32-57%), MLP/pipelining,
// instruction count, cache policy, and load balance were each varied and
// proven non-binding; DRAM sits at ~69% (188 MB/launch, mask L2-resident
// across graph replays) — also not the binder.
//
// Kernel: all 7 1x1 convs + gating folded into a per-pixel closed form:
//   f_f[c] = s1*A[c] + s4*B[c] + v_r*(s2*Sa[c] + s3*Sb[c]) + fu_b[c]
// with composite matrices WA = fuA.vi_w, WB = fuB.vi_w precomputed per
// thread. Sigmoid via MUFU.TANH: sigmoid(x) = 0.5 + 0.5*tanh(x/2), the 0.5
// factors folded into the qi/qr/vr weights at setup. Depth-1 load
// pipelining, float4 I/O, single launch.

#define HW       (512 * 512)
#define PLANE4   (HW / 4)          // 65536 float4 per plane
#define ITERS    4
#define THREADS  256

__device__ __forceinline__ float tanh_fast(float x) {
    float y;
    asm("tanh.approx.f32 %0, %1;" : "=f"(y) : "f"(x));
    return y;
}

template <bool TAIL>
__global__ void __launch_bounds__(THREADS, 4)
rim_kernel(const float* __restrict__ img, const float* __restrict__ mask,
           const float* __restrict__ qi_w, const float* __restrict__ qi_b,
           const float* __restrict__ ki_w, const float* __restrict__ ki_b,
           const float* __restrict__ vi_w, const float* __restrict__ vi_b,
           const float* __restrict__ qr_w, const float* __restrict__ qr_b,
           const float* __restrict__ kr_w, const float* __restrict__ kr_b,
           const float* __restrict__ vr_w, const float* __restrict__ vr_b,
           const float* __restrict__ fu_w, const float* __restrict__ fu_b,
           float* __restrict__ out, int n_q)
{
    // ---- per-thread coefficient setup (L1-broadcast loads) ----
    // qi, qr, vr pre-scaled by 0.5 for the tanh-based sigmoid.
    const float qiw0 = 0.5f * qi_w[0], qiw1 = 0.5f * qi_w[1],
                qiw2 = 0.5f * qi_w[2], qib  = 0.5f * qi_b[0];
    const float kiw0 = ki_w[0], kiw1 = ki_w[1], kiw2 = ki_w[2], kib = ki_b[0];
    const float qrw = 0.5f * qr_w[0], qrb = 0.5f * qr_b[0];
    const float krw = kr_w[0], krb = kr_b[0];
    const float vrw = 0.5f * vr_w[0], vrb = 0.5f * vr_b[0];

    float viw[9], vib[3];
    #pragma unroll
    for (int i = 0; i < 9; i++) viw[i] = vi_w[i];
    #pragma unroll
    for (int i = 0; i < 3; i++) vib[i] = vi_b[i];

    float WA[3][3], WB[3][3], bA[3], bB[3], Sa[3], Sb[3], fub[3];
    #pragma unroll
    for (int c = 0; c < 3; c++) {
        const float a0 = fu_w[c * 6 + 0], a1 = fu_w[c * 6 + 1], a2 = fu_w[c * 6 + 2];
        const float b0 = fu_w[c * 6 + 3], b1 = fu_w[c * 6 + 4], b2 = fu_w[c * 6 + 5];
        Sa[c] = a0 + a1 + a2;
        Sb[c] = b0 + b1 + b2;
        #pragma unroll
        for (int i = 0; i < 3; i++) {
            WA[c][i] = a0 * viw[0 * 3 + i] + a1 * viw[1 * 3 + i] + a2 * viw[2 * 3 + i];
            WB[c][i] = b0 * viw[0 * 3 + i] + b1 * viw[1 * 3 + i] + b2 * viw[2 * 3 + i];
        }
        bA[c]  = a0 * vib[0] + a1 * vib[1] + a2 * vib[2];
        bB[c]  = b0 * vib[0] + b1 * vib[1] + b2 * vib[2];
        fub[c] = fu_b[c];
    }

    auto pixel = [&](float r, float g, float bl, float m,
                     float& o0, float& o1, float& o2) {
        const float qih = fmaf(qiw2, bl, fmaf(qiw1, g, fmaf(qiw0, r, qib)));
        const float ki  = fmaf(kiw2, bl, fmaf(kiw1, g, fmaf(kiw0, r, kib)));
        const float qrh = fmaf(qrw, m, qrb);
        const float kr  = fmaf(krw, m, krb);
        const float vrh = fmaf(vrw, m, vrb);
        // sigmoid(a*b) = 0.5 + 0.5*tanh(0.5*a*b)
        const float t1 = tanh_fast(qih * ki);
        const float t2 = tanh_fast(qih * kr);
        const float t3 = tanh_fast(qrh * kr);
        const float t4 = tanh_fast(qrh * ki);
        const float s1 = fmaf(t1, 0.5f, 0.5f);
        const float s4 = fmaf(t4, 0.5f, 0.5f);
        const float p2 = fmaf(vrh, t2, vrh);   // v_r * sigmoid(q_i*k_r)
        const float p3 = fmaf(vrh, t3, vrh);   // v_r * sigmoid(q_r*k_r)
        float o[3];
        #pragma unroll
        for (int c = 0; c < 3; c++) {
            const float A  = fmaf(WA[c][2], bl, fmaf(WA[c][1], g, fmaf(WA[c][0], r, bA[c])));
            const float Bv = fmaf(WB[c][2], bl, fmaf(WB[c][1], g, fmaf(WB[c][0], r, bB[c])));
            float f = fmaf(s1, A, fub[c]);
            f = fmaf(s4, Bv, f);
            f = fmaf(p2, Sa[c], f);
            f = fmaf(p3, Sb[c], f);
            o[c] = f;
        }
        o0 = o[0]; o1 = o[1]; o2 = o[2];
    };

    const float4* img4  = reinterpret_cast<const float4*>(img);
    const float4* mask4 = reinterpret_cast<const float4*>(mask);
    float4*       out4  = reinterpret_cast<float4*>(out);

    const int tid    = blockIdx.x * THREADS + threadIdx.x;
    const int stride = gridDim.x * THREADS;

    if (!TAIL) {
        // ---- pipelined main path: prefetch iter k+1 before computing iter k ----
        int q    = tid;
        int base = (q >> 16) * (3 * PLANE4) + (q & (PLANE4 - 1));

        float4 R  = img4[base];
        float4 G  = img4[base + PLANE4];
        float4 Bc = img4[base + 2 * PLANE4];
        float4 M  = mask4[q];

        #pragma unroll
        for (int k = 0; k < ITERS; k++) {
            float4 Rn, Gn, Bn, Mn;
            int basen = base;
            if (k + 1 < ITERS) {
                const int qn = tid + (k + 1) * stride;
                basen = (qn >> 16) * (3 * PLANE4) + (qn & (PLANE4 - 1));
                Rn = img4[basen];
                Gn = img4[basen + PLANE4];
                Bn = img4[basen + 2 * PLANE4];
                Mn = mask4[qn];
            }

            float4 O0, O1, O2;
            pixel(R.x, G.x, Bc.x, M.x, O0.x, O1.x, O2.x);
            pixel(R.y, G.y, Bc.y, M.y, O0.y, O1.y, O2.y);
            pixel(R.z, G.z, Bc.z, M.z, O0.z, O1.z, O2.z);
            pixel(R.w, G.w, Bc.w, M.w, O0.w, O1.w, O2.w);

            out4[base]              = O0;
            out4[base + PLANE4]     = O1;
            out4[base + 2 * PLANE4] = O2;

            R = Rn; G = Gn; Bc = Bn; M = Mn;
            base = basen;
        }
    } else {
        for (int k = 0; k < ITERS; k++) {
            const int q = tid + k * stride;
            if (q >= n_q) break;
            const int base = (q >> 16) * (3 * PLANE4) + (q & (PLANE4 - 1));
            const float4 R  = img4[base];
            const float4 G  = img4[base + PLANE4];
            const float4 Bc = img4[base + 2 * PLANE4];
            const float4 M  = mask4[q];
            float4 O0, O1, O2;
            pixel(R.x, G.x, Bc.x, M.x, O0.x, O1.x, O2.x);
            pixel(R.y, G.y, Bc.y, M.y, O0.y, O1.y, O2.y);
            pixel(R.z, G.z, Bc.z, M.z, O0.z, O1.z, O2.z);
            pixel(R.w, G.w, Bc.w, M.w, O0.w, O1.w, O2.w);
            out4[base]              = O0;
            out4[base + PLANE4]     = O1;
            out4[base + 2 * PLANE4] = O2;
        }
    }
}

extern "C" void kernel_launch(void* const* d_in, const int* in_sizes, int n_in,
                              void* d_out, int out_size)
{
    const float* img  = (const float*)d_in[0];
    const float* mask = (const float*)d_in[1];
    const float* qi_w = (const float*)d_in[2];
    const float* qi_b = (const float*)d_in[3];
    const float* ki_w = (const float*)d_in[4];
    const float* ki_b = (const float*)d_in[5];
    const float* vi_w = (const float*)d_in[6];
    const float* vi_b = (const float*)d_in[7];
    const float* qr_w = (const float*)d_in[8];
    const float* qr_b = (const float*)d_in[9];
    const float* kr_w = (const float*)d_in[10];
    const float* kr_b = (const float*)d_in[11];
    const float* vr_w = (const float*)d_in[12];
    const float* vr_b = (const float*)d_in[13];
    const float* fu_w = (const float*)d_in[14];
    const float* fu_b = (const float*)d_in[15];

    const int n_pix = in_sizes[1];       // B*H*W
    const int n_q   = n_pix / 4;
    const int per_block = THREADS * ITERS;

    if (n_q % per_block == 0) {
        rim_kernel<false><<<n_q / per_block, THREADS>>>(
            img, mask, qi_w, qi_b, ki_w, ki_b, vi_w, vi_b,
            qr_w, qr_b, kr_w, kr_b, vr_w, vr_b, fu_w, fu_b,
            (float*)d_out, n_q);
    } else {
        rim_kernel<true><<<(n_q + per_block - 1) / per_block, THREADS>>>(
            img, mask, qi_w, qi_b, ki_w, ki_b, vi_w, vi_b,
            qr_w, qr_b, kr_w, kr_b, vr_w, vr_b, fu_w, fu_b,
            (float*)d_out, n_q);
    }
}